// round 11
// baseline (speedup 1.0000x reference)
#include <cuda_runtime.h>

#define TPB 512
#define NW  (TPB / 32)
#define CANDCAP 1024
#define C2CAP 128

// Bijective, order-preserving float -> uint key (and inverse) — fallback only.
__device__ __forceinline__ unsigned fkey(float f) {
    unsigned u = __float_as_uint(f);
    return u ^ ((unsigned)((int)u >> 31) | 0x80000000u);
}
__device__ __forceinline__ float unkey(unsigned k) {
    unsigned u = (k & 0x80000000u) ? (k ^ 0x80000000u) : ~k;
    return __uint_as_float(u);
}

template<int NITER>
__global__ __launch_bounds__(TPB, 3)
void sampler_kernel(const float* __restrict__ logits,
                    const float* __restrict__ uin,
                    float* __restrict__ out_samp,
                    float* __restrict__ out_probs,
                    int NV4)
{
    // layout: hist[0,256) | s_cx[256,1280) | s_ce[1280,2304) | s_cidx[2304,3328) | cand2[3328,3584)
    __shared__ float s_pool[3584];
    __shared__ float s_redM[NW], s_redZ[NW], s_redS[NW], s_rm[NW];
    __shared__ int   s_wi[NW];
    __shared__ int   s_cnt, s_cnt2, s_flag, s_fb, s_digit;
    __shared__ float s_G2, s_GB;

    float*  hist   = s_pool;
    float*  s_cx   = s_pool + 256;
    float*  s_ce   = s_pool + 1280;
    int*    s_cidx = reinterpret_cast<int*>(s_pool + 2304);
    float2* cand2  = reinterpret_cast<float2*>(s_pool + 3328);

    const int row  = blockIdx.x;
    const int t    = threadIdx.x;
    const int lane = t & 31;
    const int warp = t >> 5;
    const float NEG_INF = __int_as_float(0xff800000);
    const int   V = NV4 * 4;

    const float4* lg4  = reinterpret_cast<const float4*>(logits) + (size_t)row * NV4;
    const float*  urow = uin + (size_t)row * (size_t)V;
    float4*       pr4  = reinterpret_cast<float4*>(out_probs)    + (size_t)row * NV4;

    // ---------- A: load, x = logit * 1.25f (== /0.8, proven-equal), block max ----------
    float x[4 * NITER];
    float m = NEG_INF;
    #pragma unroll
    for (int k = 0; k < NITER; k++) {
        int i4 = k * TPB + t;
        float4 v = (i4 < NV4) ? __ldcs(&lg4[i4])
                              : make_float4(NEG_INF, NEG_INF, NEG_INF, NEG_INF);
        x[4*k+0] = v.x * 1.25f;
        x[4*k+1] = v.y * 1.25f;
        x[4*k+2] = v.z * 1.25f;
        x[4*k+3] = v.w * 1.25f;
        m = fmaxf(m, fmaxf(fmaxf(x[4*k+0], x[4*k+1]), fmaxf(x[4*k+2], x[4*k+3])));
    }
    for (int o = 16; o; o >>= 1) m = fmaxf(m, __shfl_xor_sync(0xffffffffu, m, o));
    if (lane == 0) s_redM[warp] = m;
    if (t < 256) hist[t] = 0.f;
    if (t == 0) { s_cnt = 0; s_cnt2 = 0; s_flag = 0; s_fb = -1; }
    __syncthreads();                                   // (1)
    {
        float mm = s_redM[0];
        #pragma unroll
        for (int i = 1; i < NW; i++) mm = fmaxf(mm, s_redM[i]);
        m = mm;
    }

    // ---------- B: cheap exp for all; fused predicated atomic gather ----------
    const float W = __logf(20.0f * (float)V) + 0.05f;  // prune window, valid all Z>=1
    const float cutoff = m - W;
    const float bsc = 256.0f / W;

    float e[4 * NITER];
    float zs = 0.f;                                    // non-candidate Z part (cheap ok: <5% mass)
    #pragma unroll
    for (int k = 0; k < NITER; k++) {
        #pragma unroll
        for (int ci = 0; ci < 4; ci++) {
            int j = 4*k + ci;
            e[j] = __expf(x[j] - m);                   // 0 for -inf padding
            if (x[j] >= cutoff) {
                int p = atomicAdd(&s_cnt, 1);
                if (p < CANDCAP) {
                    s_cx[p]   = x[j];
                    s_cidx[p] = (k * TPB + t) * 4 + ci;
                }
            } else {
                zs += e[j];
            }
        }
    }
    __syncthreads();                                   // (2)
    const int C = s_cnt;

    bool fb = (C > CANDCAP);
    float xThr = NEG_INF, keptMass = 1.f, Z = 0.f, target = 0.f;

    if (!fb) {
        // ---------- B2: precise exp over compacted candidates; hist; Z ----------
        float zp = 0.f;
        for (int i = t; i < C; i += TPB) {
            float xi = s_cx[i];
            float ei = expf(xi - m);                   // PRECISE: enters mass comparisons
            s_ce[i] = ei;
            int b = (int)((xi - cutoff) * bsc);
            b = (b > 255) ? 255 : b;
            atomicAdd(&hist[b], ei);
            zp += ei;
        }
        float zt = zs + zp;
        for (int o = 16; o; o >>= 1) zt += __shfl_xor_sync(0xffffffffu, zt, o);
        if (lane == 0) s_redZ[warp] = zt;
        __syncthreads();                               // (3)
        Z = s_redZ[0];
        #pragma unroll
        for (int i = 1; i < NW; i++) Z += s_redZ[i];
        target = 0.95f * Z;

        // ---------- C: descending scan of hist (threads 0..255), crossing bin ----------
        int   dg = 0;
        float v = 0.f, prev = 0.f;
        if (warp < 8) {
            dg = 255 - t;
            v = hist[dg];
            float iv = v;
            #pragma unroll
            for (int o = 1; o < 32; o <<= 1) {
                float n = __shfl_up_sync(0xffffffffu, iv, o);
                if (lane >= o) iv += n;
            }
            if (lane == 31) s_redS[warp] = iv;
            __syncthreads();                           // (4a)
            float woff = 0.f;
            #pragma unroll
            for (int w = 0; w < 8; w++) if (w < warp) woff += s_redS[w];
            const float incl = woff + iv;
            const float up = __shfl_up_sync(0xffffffffu, incl, 1);
            prev = (lane == 0) ? woff : up;
            if (incl > target && prev <= target) {     // unique crossing thread
                s_digit = dg; s_G2 = prev; s_flag = 1;
            }
        } else {
            __syncthreads();                           // (4b)
        }
        __syncthreads();                               // (5)
        if (s_flag == 0) {                             // FP-noise fallback (never hit)
            if (warp < 8 && v > 0.f) atomicMax(&s_fb, t);
        }
        __syncthreads();                               // (6)
        if (s_flag == 0 && warp < 8 && t == s_fb) { s_digit = dg; s_G2 = prev; }
        __syncthreads();                               // (7)
        const int   bstar = s_digit;
        const float Ab    = s_G2;

        // ---------- D: gather bin-b* candidates (tiny) ----------
        for (int i = t; i < C; i += TPB) {
            float xi = s_cx[i];
            int b = (int)((xi - cutoff) * bsc);
            b = (b > 255) ? 255 : b;
            if (b == bstar) {
                int p = atomicAdd(&s_cnt2, 1);
                if (p < C2CAP) cand2[p] = make_float2(xi, s_ce[i]);
            }
        }
        __syncthreads();                               // (8)
        const int C2 = s_cnt2;

        if (C2 <= C2CAP) {
            // ---------- E: exact all-pairs threshold within bin b* ----------
            float bx = 3.4e38f, bm = 0.f;
            for (int i = t; i < C2; i += TPB) {
                const float xi = cand2[i].x;
                float above = Ab, eq = 0.f;
                for (int j = 0; j < C2; j++) {
                    float2 cj = cand2[j];              // broadcast LDS.64
                    if (cj.x > xi) above += cj.y;
                    else if (cj.x == xi) eq += cj.y;
                }
                if (above <= target && xi < bx) { bx = xi; bm = above + eq; }
            }
            for (int o = 16; o; o >>= 1) {
                float ox = __shfl_xor_sync(0xffffffffu, bx, o);
                float om = __shfl_xor_sync(0xffffffffu, bm, o);
                if (ox < bx) { bx = ox; bm = om; }
            }
            if (lane == 0) { s_redS[warp] = bx; s_rm[warp] = bm; }
            __syncthreads();                           // (9)
            float fx = s_redS[0], fm = s_rm[0];
            #pragma unroll
            for (int i = 1; i < NW; i++)
                if (s_redS[i] < fx) { fx = s_redS[i]; fm = s_rm[i]; }
            xThr = fx; keptMass = fm;
        } else fb = true;
    }

    if (fb) {
        // ---------- fallback: exact radix select on fkey(x) (never hit; correct) ----------
        float zf = 0.f;
        #pragma unroll
        for (int j = 0; j < 4 * NITER; j++) zf += e[j];
        for (int o = 16; o; o >>= 1) zf += __shfl_xor_sync(0xffffffffu, zf, o);
        __syncthreads();
        if (lane == 0) s_redZ[warp] = zf;
        __syncthreads();
        Z = s_redZ[0];
        #pragma unroll
        for (int i = 1; i < NW; i++) Z += s_redZ[i];
        target = 0.95f * Z;

        unsigned hi = 0;
        float G = 0.f;
        float km = Z;
        #pragma unroll 1
        for (int pass = 3; pass >= 0; pass--) {
            __syncthreads();
            if (t < 256) hist[t] = 0.f;
            if (t == 0) { s_flag = 0; s_fb = -1; s_digit = 0; s_G2 = 0.f; s_GB = 0.f; }
            __syncthreads();

            const int sh = pass * 8;
            #pragma unroll
            for (int j = 0; j < 4 * NITER; j++) {
                unsigned kk = fkey(x[j]);
                bool cnd = (pass == 3) ? true : ((kk >> (sh + 8)) == hi);
                if (cnd) atomicAdd(&hist[(kk >> sh) & 255u], e[j]);
            }
            __syncthreads();

            int dgf = 0; float vf = 0.f, prevf = 0.f;
            if (warp < 8) {
                dgf = 255 - t;
                vf = hist[dgf];
                float ivf = vf;
                #pragma unroll
                for (int o = 1; o < 32; o <<= 1) {
                    float n = __shfl_up_sync(0xffffffffu, ivf, o);
                    if (lane >= o) ivf += n;
                }
                if (lane == 31) s_redS[warp] = ivf;
                __syncthreads();
                float wof = 0.f;
                #pragma unroll
                for (int w = 0; w < 8; w++) if (w < warp) wof += s_redS[w];
                const float inclf = wof + ivf;
                const float upf = __shfl_up_sync(0xffffffffu, inclf, 1);
                prevf = (lane == 0) ? wof : upf;
                const float tgt = target - G;
                if (inclf > tgt && prevf <= tgt) {
                    s_digit = dgf; s_G2 = prevf; s_GB = prevf + vf; s_flag = 1;
                }
            } else {
                __syncthreads();
            }
            __syncthreads();
            if (s_flag == 0 && warp < 8 && vf > 0.f) atomicMax(&s_fb, t);
            __syncthreads();
            if (s_flag == 0 && warp < 8 && t == s_fb) {
                s_digit = dgf; s_G2 = prevf; s_GB = prevf + vf;
            }
            __syncthreads();

            if (pass == 0) km = G + s_GB;
            G  = G + s_G2;
            hi = (hi << 8) | (unsigned)s_digit;
        }
        xThr = unkey(hi);
        keptMass = km;
    }

    const float rinv = 1.0f / fmaxf(keptMass, 1e-30f);

    // ---------- F: write probs (kept: x >= xThr); values cheap-exp (tol 1e-3) ----------
    #pragma unroll
    for (int k = 0; k < NITER; k++) {
        int i4 = k * TPB + t;
        if (i4 < NV4) {
            float4 o;
            o.x = (x[4*k+0] >= xThr) ? e[4*k+0] * rinv : 0.f;
            o.y = (x[4*k+1] >= xThr) ? e[4*k+1] * rinv : 0.f;
            o.z = (x[4*k+2] >= xThr) ? e[4*k+2] * rinv : 0.f;
            o.w = (x[4*k+3] >= xThr) ? e[4*k+3] * rinv : 0.f;
            __stcs(&pr4[i4], o);
        }
    }

    // ---------- G: Gumbel-max argmax over kept set ----------
    float best = NEG_INF;
    int   bidx = 0x7fffffff;
    if (!fb) {
        for (int i = t; i < C; i += TPB) {
            float xi = s_cx[i];
            if (xi >= xThr) {
                int idx = s_cidx[i];
                float uu = __ldcs(&urow[idx]);
                float g = -logf(-logf(uu));            // precise, kept-only
                float val = xi + g;
                if (val > best || (val == best && idx < bidx)) { best = val; bidx = idx; }
            }
        }
    } else {
        #pragma unroll
        for (int k = 0; k < NITER; k++) {
            #pragma unroll
            for (int ci = 0; ci < 4; ci++) {
                int j = 4*k + ci;
                int idx = (k * TPB + t) * 4 + ci;
                if (idx < V && x[j] >= xThr) {
                    float uu = __ldcs(&urow[idx]);
                    float g = -logf(-logf(uu));
                    float val = x[j] + g;
                    if (val > best || (val == best && idx < bidx)) { best = val; bidx = idx; }
                }
            }
        }
    }
    for (int o = 16; o; o >>= 1) {
        float v2 = __shfl_xor_sync(0xffffffffu, best, o);
        int   i2 = __shfl_xor_sync(0xffffffffu, bidx, o);
        if (v2 > best || (v2 == best && i2 < bidx)) { best = v2; bidx = i2; }
    }
    if (lane == 0) { s_redM[warp] = best; s_wi[warp] = bidx; }
    __syncthreads();                                   // (10)
    if (t == 0) {
        float bb = s_redM[0]; int bi = s_wi[0];
        #pragma unroll
        for (int i = 1; i < NW; i++) {
            float v2 = s_redM[i]; int i2 = s_wi[i];
            if (v2 > bb || (v2 == bb && i2 < bi)) { bb = v2; bi = i2; }
        }
        out_samp[row] = (float)bi;
    }
}

extern "C" void kernel_launch(void* const* d_in, const int* in_sizes, int n_in,
                              void* d_out, int out_size) {
    const float* logits = (const float*)d_in[0];
    const float* u      = (const float*)d_in[1];
    float* out = (float*)d_out;

    int total = in_sizes[0];
    int B = out_size - total;
    int V;
    if (B > 0 && total % B == 0) {
        V = total / B;
    } else {
        V = 2048;
        B = total / V;
    }
    int NV4 = V / 4;
    int nIter = (NV4 + TPB - 1) / TPB;

    if (nIter <= 1)      sampler_kernel<1><<<B, TPB>>>(logits, u, out, out + B, NV4);
    else if (nIter <= 2) sampler_kernel<2><<<B, TPB>>>(logits, u, out, out + B, NV4);
    else if (nIter <= 4) sampler_kernel<4><<<B, TPB>>>(logits, u, out, out + B, NV4);
    else                 sampler_kernel<8><<<B, TPB>>>(logits, u, out, out + B, NV4);
}

// round 12
// speedup vs baseline: 1.6311x; 1.6311x over previous
#include <cuda_runtime.h>

#define TPB 256
#define NWP 8
#define SEGCAP 128
#define C2CAP 128

// Bijective, order-preserving float -> uint key (and inverse) — fallback only.
__device__ __forceinline__ unsigned fkey(float f) {
    unsigned u = __float_as_uint(f);
    return u ^ ((unsigned)((int)u >> 31) | 0x80000000u);
}
__device__ __forceinline__ float unkey(unsigned k) {
    unsigned u = (k & 0x80000000u) ? (k ^ 0x80000000u) : ~k;
    return __uint_as_float(u);
}

template<int NITER>
__global__ __launch_bounds__(TPB, 5)
void sampler_kernel(const float* __restrict__ logits,
                    const float* __restrict__ uin,
                    float* __restrict__ out_samp,
                    float* __restrict__ out_probs,
                    int NV4)
{
    // layout: hist[0,256) | s_cx[256,1280) | s_ce[1280,2304) | s_cidx[2304,3328) | cand2[3328,3584)
    __shared__ float s_pool[3584];
    __shared__ float s_redM[NWP], s_redZ[NWP], s_redS[NWP], s_rm[NWP];
    __shared__ int   s_wi[NWP];
    __shared__ int   s_cnt2, s_flag, s_fb, s_digit, s_ovf;
    __shared__ float s_G2, s_GB;

    float*  hist   = s_pool;
    float*  s_cx   = s_pool + 256;
    float*  s_ce   = s_pool + 1280;
    int*    s_cidx = reinterpret_cast<int*>(s_pool + 2304);
    float2* cand2  = reinterpret_cast<float2*>(s_pool + 3328);

    const int row  = blockIdx.x;
    const int t    = threadIdx.x;
    const int lane = t & 31;
    const int warp = t >> 5;
    const unsigned lmask = (1u << lane) - 1u;
    const float NEG_INF = __int_as_float(0xff800000);
    const int   V = NV4 * 4;

    const float4* lg4  = reinterpret_cast<const float4*>(logits) + (size_t)row * NV4;
    const float*  urow = uin + (size_t)row * (size_t)V;
    float4*       pr4  = reinterpret_cast<float4*>(out_probs)    + (size_t)row * NV4;

    // ---------- A: load, x = logit * 1.25f (== /0.8, proven-equal), block max ----------
    float x[4 * NITER];
    float m = NEG_INF;
    #pragma unroll
    for (int k = 0; k < NITER; k++) {
        int i4 = k * TPB + t;
        float4 v = (i4 < NV4) ? __ldcs(&lg4[i4])
                              : make_float4(NEG_INF, NEG_INF, NEG_INF, NEG_INF);
        x[4*k+0] = v.x * 1.25f;
        x[4*k+1] = v.y * 1.25f;
        x[4*k+2] = v.z * 1.25f;
        x[4*k+3] = v.w * 1.25f;
        m = fmaxf(m, fmaxf(fmaxf(x[4*k+0], x[4*k+1]), fmaxf(x[4*k+2], x[4*k+3])));
    }
    for (int o = 16; o; o >>= 1) m = fmaxf(m, __shfl_xor_sync(0xffffffffu, m, o));
    if (lane == 0) s_redM[warp] = m;
    hist[t] = 0.f;
    if (t == 0) { s_cnt2 = 0; s_flag = 0; s_fb = -1; s_ovf = 0; }
    __syncthreads();                                   // (1)
    {
        float mm = s_redM[0];
        #pragma unroll
        for (int i = 1; i < NWP; i++) mm = fmaxf(mm, s_redM[i]);
        m = mm;
    }

    // ---------- B: cheap exp for all; warp-segment ballot gather (atomic-free) ----------
    const float W = __logf(20.0f * (float)V) + 0.05f;  // prune window, valid all Z>=1
    const float cutoff = m - W;
    const float bsc = 256.0f / W;
    const int wseg = warp * SEGCAP;

    float e[4 * NITER];
    float zs = 0.f;                                    // non-candidate Z part (cheap ok: <5% mass)
    int off = 0;
    #pragma unroll
    for (int k = 0; k < NITER; k++) {
        #pragma unroll
        for (int ci = 0; ci < 4; ci++) {
            int j = 4*k + ci;
            e[j] = __expf(x[j] - m);                   // 0 for -inf padding
            bool pred = (x[j] >= cutoff);
            unsigned bal = __ballot_sync(0xffffffffu, pred);
            if (pred) {
                int p = off + __popc(bal & lmask);
                if (p < SEGCAP) {
                    s_cx[wseg + p]   = x[j];
                    s_cidx[wseg + p] = (k * TPB + t) * 4 + ci;
                }
            } else {
                zs += e[j];
            }
            off += __popc(bal);
        }
    }
    if (off > SEGCAP && lane == 0) s_ovf = 1;
    const int cnt = (off < SEGCAP) ? off : SEGCAP;

    // ---------- B2 (warp-local, no barrier): precise exp; hist; Z ----------
    float zp = 0.f;
    for (int i = lane; i < cnt; i += 32) {
        float xi = s_cx[wseg + i];
        float ei = expf(xi - m);                       // PRECISE: enters mass comparisons
        s_ce[wseg + i] = ei;
        int b = (int)((xi - cutoff) * bsc);
        b = (b > 255) ? 255 : b;
        atomicAdd(&hist[b], ei);
        zp += ei;
    }
    float zt = zs + zp;
    for (int o = 16; o; o >>= 1) zt += __shfl_xor_sync(0xffffffffu, zt, o);
    if (lane == 0) s_redZ[warp] = zt;
    __syncthreads();                                   // (2)

    bool fb = (s_ovf != 0);
    float Z = s_redZ[0];
    #pragma unroll
    for (int i = 1; i < NWP; i++) Z += s_redZ[i];
    float target = 0.95f * Z;
    float xThr = NEG_INF, keptMass = 1.f;

    if (!fb) {
        // ---------- C: descending scan of hist, crossing bin ----------
        const int dg = 255 - t;
        const float v = hist[dg];
        float iv = v;
        #pragma unroll
        for (int o = 1; o < 32; o <<= 1) {
            float n = __shfl_up_sync(0xffffffffu, iv, o);
            if (lane >= o) iv += n;
        }
        if (lane == 31) s_redS[warp] = iv;
        __syncthreads();                               // (3)
        float woff = 0.f;
        #pragma unroll
        for (int w = 0; w < NWP; w++) if (w < warp) woff += s_redS[w];
        const float incl = woff + iv;
        const float up = __shfl_up_sync(0xffffffffu, incl, 1);
        const float prev = (lane == 0) ? woff : up;

        if (incl > target && prev <= target) {         // unique crossing thread
            s_digit = dg; s_G2 = prev; s_flag = 1;
        }
        __syncthreads();                               // (4)
        if (s_flag == 0) {                             // FP-noise fallback (never hit)
            if (v > 0.f) atomicMax(&s_fb, t);
            __syncthreads();
            if (t == s_fb) { s_digit = dg; s_G2 = prev; }
            __syncthreads();
        }
        const int   bstar = s_digit;
        const float Ab    = s_G2;

        // ---------- D: gather bin-b* candidates from own segment (tiny) ----------
        for (int i = lane; i < cnt; i += 32) {
            float xi = s_cx[wseg + i];
            int b = (int)((xi - cutoff) * bsc);
            b = (b > 255) ? 255 : b;
            if (b == bstar) {
                int p = atomicAdd(&s_cnt2, 1);
                if (p < C2CAP) cand2[p] = make_float2(xi, s_ce[wseg + i]);
            }
        }
        __syncthreads();                               // (5)
        const int C2 = s_cnt2;

        if (C2 <= C2CAP) {
            // ---------- E: exact all-pairs threshold within bin b* ----------
            float bx = 3.4e38f, bm = 0.f;
            for (int i = t; i < C2; i += TPB) {
                const float xi = cand2[i].x;
                float above = Ab, eq = 0.f;
                for (int j = 0; j < C2; j++) {
                    float2 cj = cand2[j];              // broadcast LDS.64
                    if (cj.x > xi) above += cj.y;
                    else if (cj.x == xi) eq += cj.y;
                }
                if (above <= target && xi < bx) { bx = xi; bm = above + eq; }
            }
            for (int o = 16; o; o >>= 1) {
                float ox = __shfl_xor_sync(0xffffffffu, bx, o);
                float om = __shfl_xor_sync(0xffffffffu, bm, o);
                if (ox < bx) { bx = ox; bm = om; }
            }
            if (lane == 0) { s_redS[warp] = bx; s_rm[warp] = bm; }
            __syncthreads();                           // (6)
            float fx = s_redS[0], fm = s_rm[0];
            #pragma unroll
            for (int i = 1; i < NWP; i++)
                if (s_redS[i] < fx) { fx = s_redS[i]; fm = s_rm[i]; }
            xThr = fx; keptMass = fm;
        } else fb = true;
    }

    if (fb) {
        // ---------- fallback: exact radix select on fkey(x) (never hit; correct) ----------
        float zf = 0.f;
        #pragma unroll
        for (int j = 0; j < 4 * NITER; j++) zf += e[j];
        for (int o = 16; o; o >>= 1) zf += __shfl_xor_sync(0xffffffffu, zf, o);
        __syncthreads();
        if (lane == 0) s_redZ[warp] = zf;
        __syncthreads();
        Z = s_redZ[0];
        #pragma unroll
        for (int i = 1; i < NWP; i++) Z += s_redZ[i];
        target = 0.95f * Z;

        unsigned hi = 0;
        float G = 0.f;
        float km = Z;
        #pragma unroll 1
        for (int pass = 3; pass >= 0; pass--) {
            __syncthreads();
            hist[t] = 0.f;
            if (t == 0) { s_flag = 0; s_fb = -1; s_digit = 0; s_G2 = 0.f; s_GB = 0.f; }
            __syncthreads();

            const int sh = pass * 8;
            #pragma unroll
            for (int j = 0; j < 4 * NITER; j++) {
                unsigned kk = fkey(x[j]);
                bool cnd = (pass == 3) ? true : ((kk >> (sh + 8)) == hi);
                if (cnd) atomicAdd(&hist[(kk >> sh) & 255u], e[j]);
            }
            __syncthreads();

            const int dgf = 255 - t;
            float vf = hist[dgf];
            float ivf = vf;
            #pragma unroll
            for (int o = 1; o < 32; o <<= 1) {
                float n = __shfl_up_sync(0xffffffffu, ivf, o);
                if (lane >= o) ivf += n;
            }
            if (lane == 31) s_redS[warp] = ivf;
            __syncthreads();
            float wof = 0.f;
            #pragma unroll
            for (int w = 0; w < NWP; w++) if (w < warp) wof += s_redS[w];
            const float inclf = wof + ivf;
            const float upf = __shfl_up_sync(0xffffffffu, inclf, 1);
            const float prevf = (lane == 0) ? wof : upf;

            const float tgt = target - G;
            if (inclf > tgt && prevf <= tgt) {
                s_digit = dgf; s_G2 = prevf; s_GB = prevf + vf; s_flag = 1;
            }
            __syncthreads();
            if (s_flag == 0 && vf > 0.f) atomicMax(&s_fb, t);
            __syncthreads();
            if (s_flag == 0 && t == s_fb) {
                s_digit = dgf; s_G2 = prevf; s_GB = prevf + vf;
            }
            __syncthreads();

            if (pass == 0) km = G + s_GB;
            G  = G + s_G2;
            hi = (hi << 8) | (unsigned)s_digit;
        }
        xThr = unkey(hi);
        keptMass = km;
    }

    const float rinv = 1.0f / fmaxf(keptMass, 1e-30f);

    // ---------- F: write probs (kept: x >= xThr); values cheap-exp (tol 1e-3) ----------
    #pragma unroll
    for (int k = 0; k < NITER; k++) {
        int i4 = k * TPB + t;
        if (i4 < NV4) {
            float4 o;
            o.x = (x[4*k+0] >= xThr) ? e[4*k+0] * rinv : 0.f;
            o.y = (x[4*k+1] >= xThr) ? e[4*k+1] * rinv : 0.f;
            o.z = (x[4*k+2] >= xThr) ? e[4*k+2] * rinv : 0.f;
            o.w = (x[4*k+3] >= xThr) ? e[4*k+3] * rinv : 0.f;
            __stcs(&pr4[i4], o);
        }
    }

    // ---------- G: Gumbel-max argmax over kept set ----------
    float best = NEG_INF;
    int   bidx = 0x7fffffff;
    if (!fb) {
        for (int i = lane; i < cnt; i += 32) {         // own warp segment
            float xi = s_cx[wseg + i];
            if (xi >= xThr) {
                int idx = s_cidx[wseg + i];
                float uu = __ldcs(&urow[idx]);
                float g = -logf(-logf(uu));            // precise, kept-only
                float val = xi + g;
                if (val > best || (val == best && idx < bidx)) { best = val; bidx = idx; }
            }
        }
    } else {
        #pragma unroll
        for (int k = 0; k < NITER; k++) {
            #pragma unroll
            for (int ci = 0; ci < 4; ci++) {
                int j = 4*k + ci;
                int idx = (k * TPB + t) * 4 + ci;
                if (idx < V && x[j] >= xThr) {
                    float uu = __ldcs(&urow[idx]);
                    float g = -logf(-logf(uu));
                    float val = x[j] + g;
                    if (val > best || (val == best && idx < bidx)) { best = val; bidx = idx; }
                }
            }
        }
    }
    for (int o = 16; o; o >>= 1) {
        float v2 = __shfl_xor_sync(0xffffffffu, best, o);
        int   i2 = __shfl_xor_sync(0xffffffffu, bidx, o);
        if (v2 > best || (v2 == best && i2 < bidx)) { best = v2; bidx = i2; }
    }
    if (lane == 0) { s_redM[warp] = best; s_wi[warp] = bidx; }
    __syncthreads();                                   // (7)
    if (t == 0) {
        float bb = s_redM[0]; int bi = s_wi[0];
        #pragma unroll
        for (int i = 1; i < NWP; i++) {
            float v2 = s_redM[i]; int i2 = s_wi[i];
            if (v2 > bb || (v2 == bb && i2 < bi)) { bb = v2; bi = i2; }
        }
        out_samp[row] = (float)bi;
    }
}

extern "C" void kernel_launch(void* const* d_in, const int* in_sizes, int n_in,
                              void* d_out, int out_size) {
    const float* logits = (const float*)d_in[0];
    const float* u      = (const float*)d_in[1];
    float* out = (float*)d_out;

    int total = in_sizes[0];
    int B = out_size - total;
    int V;
    if (B > 0 && total % B == 0) {
        V = total / B;
    } else {
        V = 2048;
        B = total / V;
    }
    int NV4 = V / 4;
    int nIter = (NV4 + TPB - 1) / TPB;

    if (nIter <= 1)      sampler_kernel<1><<<B, TPB>>>(logits, u, out, out + B, NV4);
    else if (nIter <= 2) sampler_kernel<2><<<B, TPB>>>(logits, u, out, out + B, NV4);
    else if (nIter <= 4) sampler_kernel<4><<<B, TPB>>>(logits, u, out, out + B, NV4);
    else                 sampler_kernel<8><<<B, TPB>>>(logits, u, out, out + B, NV4);
}

// round 13
// speedup vs baseline: 1.8135x; 1.1118x over previous
#include <cuda_runtime.h>

#define TPB 256
#define NWP 8
#define SEGCAP 128
#define C2CAP 128

// Bijective, order-preserving float -> uint key (and inverse) — fallback only.
__device__ __forceinline__ unsigned fkey(float f) {
    unsigned u = __float_as_uint(f);
    return u ^ ((unsigned)((int)u >> 31) | 0x80000000u);
}
__device__ __forceinline__ float unkey(unsigned k) {
    unsigned u = (k & 0x80000000u) ? (k ^ 0x80000000u) : ~k;
    return __uint_as_float(u);
}

template<int NITER>
__global__ __launch_bounds__(TPB, 6)
void sampler_kernel(const float* __restrict__ logits,
                    const float* __restrict__ uin,
                    float* __restrict__ out_samp,
                    float* __restrict__ out_probs,
                    int NV4)
{
    // layout: hist[0,256) | s_cx[256,1280) | s_ce[1280,2304) | s_cidx[2304,3328) | cand2[3328,3584)
    __shared__ float s_pool[3584];
    __shared__ float s_redM[NWP], s_redZ[NWP], s_redS[NWP], s_rm[NWP];
    __shared__ int   s_wi[NWP];
    __shared__ int   s_cnt2, s_flag, s_fb, s_digit, s_ovf;
    __shared__ float s_G2, s_GB;

    float*  hist   = s_pool;
    float*  s_cx   = s_pool + 256;
    float*  s_ce   = s_pool + 1280;
    int*    s_cidx = reinterpret_cast<int*>(s_pool + 2304);
    float2* cand2  = reinterpret_cast<float2*>(s_pool + 3328);

    const int row  = blockIdx.x;
    const int t    = threadIdx.x;
    const int lane = t & 31;
    const int warp = t >> 5;
    const unsigned lmask = (1u << lane) - 1u;
    const float NEG_INF = __int_as_float(0xff800000);
    const int   V = NV4 * 4;

    const float4* lg4  = reinterpret_cast<const float4*>(logits) + (size_t)row * NV4;
    const float*  urow = uin + (size_t)row * (size_t)V;
    float*        prow = out_probs + (size_t)row * (size_t)V;
    float4*       pr4  = reinterpret_cast<float4*>(out_probs)    + (size_t)row * NV4;

    // ---------- A: load, x = logit * 1.25f (== /0.8, proven-equal), block max;
    //              zero-fill probs (scatter overwrites kept entries later) ----------
    float x[4 * NITER];
    float m = NEG_INF;
    const float4 zero4 = make_float4(0.f, 0.f, 0.f, 0.f);
    #pragma unroll
    for (int k = 0; k < NITER; k++) {
        int i4 = k * TPB + t;
        float4 v = (i4 < NV4) ? __ldcs(&lg4[i4])
                              : make_float4(NEG_INF, NEG_INF, NEG_INF, NEG_INF);
        if (i4 < NV4) __stcs(&pr4[i4], zero4);
        x[4*k+0] = v.x * 1.25f;
        x[4*k+1] = v.y * 1.25f;
        x[4*k+2] = v.z * 1.25f;
        x[4*k+3] = v.w * 1.25f;
        m = fmaxf(m, fmaxf(fmaxf(x[4*k+0], x[4*k+1]), fmaxf(x[4*k+2], x[4*k+3])));
    }
    for (int o = 16; o; o >>= 1) m = fmaxf(m, __shfl_xor_sync(0xffffffffu, m, o));
    if (lane == 0) s_redM[warp] = m;
    hist[t] = 0.f;
    if (t == 0) { s_cnt2 = 0; s_flag = 0; s_fb = -1; s_ovf = 0; }
    __syncthreads();                                   // (1)
    {
        float mm = s_redM[0];
        #pragma unroll
        for (int i = 1; i < NWP; i++) mm = fmaxf(mm, s_redM[i]);
        m = mm;
    }

    // ---------- B: cheap exp (zs only); warp-segment ballot gather (atomic-free) ----------
    const float W = __logf(20.0f * (float)V) + 0.05f;  // prune window, valid all Z>=1
    const float cutoff = m - W;
    const float bsc = 256.0f / W;
    const int wseg = warp * SEGCAP;

    float zs = 0.f;                                    // non-candidate Z part (cheap ok: <5% mass)
    int off = 0;
    #pragma unroll
    for (int k = 0; k < NITER; k++) {
        #pragma unroll
        for (int ci = 0; ci < 4; ci++) {
            int j = 4*k + ci;
            bool pred = (x[j] >= cutoff);
            unsigned bal = __ballot_sync(0xffffffffu, pred);
            if (pred) {
                int p = off + __popc(bal & lmask);
                if (p < SEGCAP) {
                    s_cx[wseg + p]   = x[j];
                    s_cidx[wseg + p] = (k * TPB + t) * 4 + ci;
                }
            } else {
                zs += __expf(x[j] - m);                // 0 for -inf padding
            }
            off += __popc(bal);
        }
    }
    if (off > SEGCAP && lane == 0) s_ovf = 1;
    const int cnt = (off < SEGCAP) ? off : SEGCAP;

    // ---------- B2 (warp-local, no barrier): precise exp; hist; Z ----------
    float zp = 0.f;
    for (int i = lane; i < cnt; i += 32) {
        float xi = s_cx[wseg + i];
        float ei = expf(xi - m);                       // PRECISE: enters mass comparisons
        s_ce[wseg + i] = ei;
        int b = (int)((xi - cutoff) * bsc);
        b = (b > 255) ? 255 : b;
        atomicAdd(&hist[b], ei);
        zp += ei;
    }
    float zt = zs + zp;
    for (int o = 16; o; o >>= 1) zt += __shfl_xor_sync(0xffffffffu, zt, o);
    if (lane == 0) s_redZ[warp] = zt;
    __syncthreads();                                   // (2)

    bool fb = (s_ovf != 0);
    float Z = s_redZ[0];
    #pragma unroll
    for (int i = 1; i < NWP; i++) Z += s_redZ[i];
    float target = 0.95f * Z;
    float xThr = NEG_INF, keptMass = 1.f;

    if (!fb) {
        // ---------- C: descending scan of hist, crossing bin ----------
        const int dg = 255 - t;
        const float v = hist[dg];
        float iv = v;
        #pragma unroll
        for (int o = 1; o < 32; o <<= 1) {
            float n = __shfl_up_sync(0xffffffffu, iv, o);
            if (lane >= o) iv += n;
        }
        if (lane == 31) s_redS[warp] = iv;
        __syncthreads();                               // (3)
        float woff = 0.f;
        #pragma unroll
        for (int w = 0; w < NWP; w++) if (w < warp) woff += s_redS[w];
        const float incl = woff + iv;
        const float up = __shfl_up_sync(0xffffffffu, incl, 1);
        const float prev = (lane == 0) ? woff : up;

        if (incl > target && prev <= target) {         // unique crossing thread
            s_digit = dg; s_G2 = prev; s_flag = 1;
        }
        __syncthreads();                               // (4)
        if (s_flag == 0) {                             // FP-noise fallback (never hit)
            if (v > 0.f) atomicMax(&s_fb, t);
            __syncthreads();
            if (t == s_fb) { s_digit = dg; s_G2 = prev; }
            __syncthreads();
        }
        const int   bstar = s_digit;
        const float Ab    = s_G2;

        // ---------- D: gather bin-b* candidates from own segment (tiny) ----------
        for (int i = lane; i < cnt; i += 32) {
            float xi = s_cx[wseg + i];
            int b = (int)((xi - cutoff) * bsc);
            b = (b > 255) ? 255 : b;
            if (b == bstar) {
                int p = atomicAdd(&s_cnt2, 1);
                if (p < C2CAP) cand2[p] = make_float2(xi, s_ce[wseg + i]);
            }
        }
        __syncthreads();                               // (5)
        const int C2 = s_cnt2;

        if (C2 <= C2CAP) {
            // ---------- E: exact all-pairs threshold within bin b* ----------
            float bx = 3.4e38f, bm = 0.f;
            for (int i = t; i < C2; i += TPB) {
                const float xi = cand2[i].x;
                float above = Ab, eq = 0.f;
                for (int j = 0; j < C2; j++) {
                    float2 cj = cand2[j];              // broadcast LDS.64
                    if (cj.x > xi) above += cj.y;
                    else if (cj.x == xi) eq += cj.y;
                }
                if (above <= target && xi < bx) { bx = xi; bm = above + eq; }
            }
            for (int o = 16; o; o >>= 1) {
                float ox = __shfl_xor_sync(0xffffffffu, bx, o);
                float om = __shfl_xor_sync(0xffffffffu, bm, o);
                if (ox < bx) { bx = ox; bm = om; }
            }
            if (lane == 0) { s_redS[warp] = bx; s_rm[warp] = bm; }
            __syncthreads();                           // (6)
            float fx = s_redS[0], fm = s_rm[0];
            #pragma unroll
            for (int i = 1; i < NWP; i++)
                if (s_redS[i] < fx) { fx = s_redS[i]; fm = s_rm[i]; }
            xThr = fx; keptMass = fm;
        } else fb = true;
    }

    if (!fb) {
        const float rinv = 1.0f / fmaxf(keptMass, 1e-30f);

        // ---------- F: scatter kept probs (precise values) + Gumbel, fused ----------
        float best = NEG_INF;
        int   bidx = 0x7fffffff;
        for (int i = lane; i < cnt; i += 32) {         // own warp segment
            float xi = s_cx[wseg + i];
            if (xi >= xThr) {
                int idx = s_cidx[wseg + i];
                prow[idx] = s_ce[wseg + i] * rinv;     // overwrite zero-fill
                float uu = __ldcs(&urow[idx]);
                float g = -logf(-logf(uu));            // precise, kept-only
                float val = xi + g;
                if (val > best || (val == best && idx < bidx)) { best = val; bidx = idx; }
            }
        }
        for (int o = 16; o; o >>= 1) {
            float v2 = __shfl_xor_sync(0xffffffffu, best, o);
            int   i2 = __shfl_xor_sync(0xffffffffu, bidx, o);
            if (v2 > best || (v2 == best && i2 < bidx)) { best = v2; bidx = i2; }
        }
        if (lane == 0) { s_redM[warp] = best; s_wi[warp] = bidx; }
        __syncthreads();                               // (7)
        if (t == 0) {
            float bb = s_redM[0]; int bi = s_wi[0];
            #pragma unroll
            for (int i = 1; i < NWP; i++) {
                float v2 = s_redM[i]; int i2 = s_wi[i];
                if (v2 > bb || (v2 == bb && i2 < bi)) { bb = v2; bi = i2; }
            }
            out_samp[row] = (float)bi;
        }
        return;
    }

    // ================= fallback: exact radix select (never hit; correct) =================
    {
        float zf = 0.f;
        #pragma unroll
        for (int j = 0; j < 4 * NITER; j++) zf += __expf(x[j] - m);
        for (int o = 16; o; o >>= 1) zf += __shfl_xor_sync(0xffffffffu, zf, o);
        __syncthreads();
        if (lane == 0) s_redZ[warp] = zf;
        __syncthreads();
        Z = s_redZ[0];
        #pragma unroll
        for (int i = 1; i < NWP; i++) Z += s_redZ[i];
        target = 0.95f * Z;

        unsigned hi = 0;
        float G = 0.f;
        float km = Z;
        #pragma unroll 1
        for (int pass = 3; pass >= 0; pass--) {
            __syncthreads();
            hist[t] = 0.f;
            if (t == 0) { s_flag = 0; s_fb = -1; s_digit = 0; s_G2 = 0.f; s_GB = 0.f; }
            __syncthreads();

            const int sh = pass * 8;
            #pragma unroll
            for (int j = 0; j < 4 * NITER; j++) {
                unsigned kk = fkey(x[j]);
                bool cnd = (pass == 3) ? true : ((kk >> (sh + 8)) == hi);
                if (cnd) atomicAdd(&hist[(kk >> sh) & 255u], __expf(x[j] - m));
            }
            __syncthreads();

            const int dgf = 255 - t;
            float vf = hist[dgf];
            float ivf = vf;
            #pragma unroll
            for (int o = 1; o < 32; o <<= 1) {
                float n = __shfl_up_sync(0xffffffffu, ivf, o);
                if (lane >= o) ivf += n;
            }
            if (lane == 31) s_redS[warp] = ivf;
            __syncthreads();
            float wof = 0.f;
            #pragma unroll
            for (int w = 0; w < NWP; w++) if (w < warp) wof += s_redS[w];
            const float inclf = wof + ivf;
            const float upf = __shfl_up_sync(0xffffffffu, inclf, 1);
            const float prevf = (lane == 0) ? wof : upf;

            const float tgt = target - G;
            if (inclf > tgt && prevf <= tgt) {
                s_digit = dgf; s_G2 = prevf; s_GB = prevf + vf; s_flag = 1;
            }
            __syncthreads();
            if (s_flag == 0 && vf > 0.f) atomicMax(&s_fb, t);
            __syncthreads();
            if (s_flag == 0 && t == s_fb) {
                s_digit = dgf; s_G2 = prevf; s_GB = prevf + vf;
            }
            __syncthreads();

            if (pass == 0) km = G + s_GB;
            G  = G + s_G2;
            hi = (hi << 8) | (unsigned)s_digit;
        }
        xThr = unkey(hi);
        keptMass = km;
    }

    {
        const float rinv = 1.0f / fmaxf(keptMass, 1e-30f);
        float best = NEG_INF;
        int   bidx = 0x7fffffff;
        #pragma unroll
        for (int k = 0; k < NITER; k++) {
            #pragma unroll
            for (int ci = 0; ci < 4; ci++) {
                int j = 4*k + ci;
                int idx = (k * TPB + t) * 4 + ci;
                if (idx < V && x[j] >= xThr) {
                    prow[idx] = __expf(x[j] - m) * rinv;
                    float uu = __ldcs(&urow[idx]);
                    float g = -logf(-logf(uu));
                    float val = x[j] + g;
                    if (val > best || (val == best && idx < bidx)) { best = val; bidx = idx; }
                }
            }
        }
        for (int o = 16; o; o >>= 1) {
            float v2 = __shfl_xor_sync(0xffffffffu, best, o);
            int   i2 = __shfl_xor_sync(0xffffffffu, bidx, o);
            if (v2 > best || (v2 == best && i2 < bidx)) { best = v2; bidx = i2; }
        }
        if (lane == 0) { s_redM[warp] = best; s_wi[warp] = bidx; }
        __syncthreads();
        if (t == 0) {
            float bb = s_redM[0]; int bi = s_wi[0];
            #pragma unroll
            for (int i = 1; i < NWP; i++) {
                float v2 = s_redM[i]; int i2 = s_wi[i];
                if (v2 > bb || (v2 == bb && i2 < bi)) { bb = v2; bi = i2; }
            }
            out_samp[row] = (float)bi;
        }
    }
}

extern "C" void kernel_launch(void* const* d_in, const int* in_sizes, int n_in,
                              void* d_out, int out_size) {
    const float* logits = (const float*)d_in[0];
    const float* u      = (const float*)d_in[1];
    float* out = (float*)d_out;

    int total = in_sizes[0];
    int B = out_size - total;
    int V;
    if (B > 0 && total % B == 0) {
        V = total / B;
    } else {
        V = 2048;
        B = total / V;
    }
    int NV4 = V / 4;
    int nIter = (NV4 + TPB - 1) / TPB;

    if (nIter <= 1)      sampler_kernel<1><<<B, TPB>>>(logits, u, out, out + B, NV4);
    else if (nIter <= 2) sampler_kernel<2><<<B, TPB>>>(logits, u, out, out + B, NV4);
    else if (nIter <= 4) sampler_kernel<4><<<B, TPB>>>(logits, u, out, out + B, NV4);
    else                 sampler_kernel<8><<<B, TPB>>>(logits, u, out, out + B, NV4);
}

// round 14
// speedup vs baseline: 1.8681x; 1.0301x over previous
#include <cuda_runtime.h>

#define TPB 256
#define NWP 8
#define SEGCAP 128
#define C2CAP 128
#define KCAP 128

// Bijective, order-preserving float -> uint key (and inverse) — fallback only.
__device__ __forceinline__ unsigned fkey(float f) {
    unsigned u = __float_as_uint(f);
    return u ^ ((unsigned)((int)u >> 31) | 0x80000000u);
}
__device__ __forceinline__ float unkey(unsigned k) {
    unsigned u = (k & 0x80000000u) ? (k ^ 0x80000000u) : ~k;
    return __uint_as_float(u);
}

template<int NITER, bool EXACT>
__global__ __launch_bounds__(TPB, 6)
void sampler_kernel(const float* __restrict__ logits,
                    const float* __restrict__ uin,
                    float* __restrict__ out_samp,
                    float* __restrict__ out_probs,
                    int NV4)
{
    // layout: hist[0,256) | s_cx[256,1280) | s_ce[1280,2304) | s_cidx[2304,3328) | cand2/kept[3328,3584)
    __shared__ float s_pool[3584];
    __shared__ float s_redM[NWP], s_redZ[NWP], s_redS[NWP], s_rm[NWP];
    __shared__ int   s_wi[NWP];
    __shared__ int   s_cnt2, s_cnt3, s_flag, s_fb, s_digit, s_ovf;
    __shared__ float s_G2, s_GB;

    float*  hist   = s_pool;
    float*  s_cx   = s_pool + 256;
    float*  s_ce   = s_pool + 1280;
    int*    s_cidx = reinterpret_cast<int*>(s_pool + 2304);
    float2* cand2  = reinterpret_cast<float2*>(s_pool + 3328);

    const int row  = blockIdx.x;
    const int t    = threadIdx.x;
    const int lane = t & 31;
    const int warp = t >> 5;
    const unsigned lmask = (1u << lane) - 1u;
    const float NEG_INF = __int_as_float(0xff800000);
    const int   V = NV4 * 4;

    const float4* lg4  = reinterpret_cast<const float4*>(logits) + (size_t)row * NV4;
    const float*  urow = uin + (size_t)row * (size_t)V;
    float*        prow = out_probs + (size_t)row * (size_t)V;
    float4*       pr4  = reinterpret_cast<float4*>(out_probs)    + (size_t)row * NV4;

    // ---------- A: load, x = logit * 1.25f (== /0.8, proven-equal), block max;
    //              zero-fill probs (scatter overwrites kept entries later) ----------
    float x[4 * NITER];
    float m = NEG_INF;
    const float4 zero4 = make_float4(0.f, 0.f, 0.f, 0.f);
    #pragma unroll
    for (int k = 0; k < NITER; k++) {
        int i4 = k * TPB + t;
        bool inb = EXACT || (i4 < NV4);
        float4 v = inb ? __ldcs(&lg4[i4])
                       : make_float4(NEG_INF, NEG_INF, NEG_INF, NEG_INF);
        if (inb) __stcs(&pr4[i4], zero4);
        x[4*k+0] = v.x * 1.25f;
        x[4*k+1] = v.y * 1.25f;
        x[4*k+2] = v.z * 1.25f;
        x[4*k+3] = v.w * 1.25f;
        m = fmaxf(m, fmaxf(fmaxf(x[4*k+0], x[4*k+1]), fmaxf(x[4*k+2], x[4*k+3])));
    }
    for (int o = 16; o; o >>= 1) m = fmaxf(m, __shfl_xor_sync(0xffffffffu, m, o));
    if (lane == 0) s_redM[warp] = m;
    hist[t] = 0.f;
    if (t == 0) { s_cnt2 = 0; s_cnt3 = 0; s_flag = 0; s_fb = -1; s_ovf = 0; }
    __syncthreads();                                   // (1)
    {
        float mm = s_redM[0];
        #pragma unroll
        for (int i = 1; i < NWP; i++) mm = fmaxf(mm, s_redM[i]);
        m = mm;
    }

    // ---------- B: cheap exp (zs only); warp-segment ballot gather (atomic-free) ----------
    const float W = __logf(20.0f * (float)V) + 0.05f;  // prune window, valid all Z>=1
    const float cutoff = m - W;
    const float bsc = 256.0f / W;
    const int wseg = warp * SEGCAP;

    float zs = 0.f;                                    // non-candidate Z part (cheap ok: <5% mass)
    int off = 0;
    #pragma unroll
    for (int k = 0; k < NITER; k++) {
        #pragma unroll
        for (int ci = 0; ci < 4; ci++) {
            int j = 4*k + ci;
            bool pred = (x[j] >= cutoff);
            unsigned bal = __ballot_sync(0xffffffffu, pred);
            if (pred) {
                int p = off + __popc(bal & lmask);
                if (p < SEGCAP) {
                    s_cx[wseg + p]   = x[j];
                    s_cidx[wseg + p] = (k * TPB + t) * 4 + ci;
                }
            } else {
                zs += __expf(x[j] - m);                // 0 for -inf padding
            }
            off += __popc(bal);
        }
    }
    if (off > SEGCAP && lane == 0) s_ovf = 1;
    const int cnt = (off < SEGCAP) ? off : SEGCAP;

    // ---------- B2 (warp-local, no barrier): precise exp; hist; Z ----------
    float zp = 0.f;
    for (int base = 0; base < cnt; base += 32) {
        int i = base + lane;
        if (i < cnt) {
            float xi = s_cx[wseg + i];
            float ei = expf(xi - m);                   // PRECISE: enters mass comparisons
            s_ce[wseg + i] = ei;
            int b = (int)((xi - cutoff) * bsc);
            b = (b > 255) ? 255 : b;
            atomicAdd(&hist[b], ei);
            zp += ei;
        }
    }
    float zt = zs + zp;
    for (int o = 16; o; o >>= 1) zt += __shfl_xor_sync(0xffffffffu, zt, o);
    if (lane == 0) s_redZ[warp] = zt;
    __syncthreads();                                   // (2)

    bool fb = (s_ovf != 0);
    float Z = s_redZ[0];
    #pragma unroll
    for (int i = 1; i < NWP; i++) Z += s_redZ[i];
    float target = 0.95f * Z;
    float xThr = NEG_INF, keptMass = 1.f;

    if (!fb) {
        // ---------- C: descending scan of hist, crossing bin ----------
        const int dg = 255 - t;
        const float v = hist[dg];
        float iv = v;
        #pragma unroll
        for (int o = 1; o < 32; o <<= 1) {
            float n = __shfl_up_sync(0xffffffffu, iv, o);
            if (lane >= o) iv += n;
        }
        if (lane == 31) s_redS[warp] = iv;
        __syncthreads();                               // (3)
        float woff = 0.f;
        #pragma unroll
        for (int w = 0; w < NWP; w++) if (w < warp) woff += s_redS[w];
        const float incl = woff + iv;
        const float up = __shfl_up_sync(0xffffffffu, incl, 1);
        const float prev = (lane == 0) ? woff : up;

        if (incl > target && prev <= target) {         // unique crossing thread
            s_digit = dg; s_G2 = prev; s_flag = 1;
        }
        __syncthreads();                               // (4)
        if (s_flag == 0) {                             // FP-noise fallback (never hit)
            if (v > 0.f) atomicMax(&s_fb, t);
            __syncthreads();
            if (t == s_fb) { s_digit = dg; s_G2 = prev; }
            __syncthreads();
        }
        const int   bstar = s_digit;
        const float Ab    = s_G2;

        // ---------- D: gather bin-b* candidates from own segment (tiny) ----------
        for (int base = 0; base < cnt; base += 32) {
            int i = base + lane;
            if (i < cnt) {
                float xi = s_cx[wseg + i];
                int b = (int)((xi - cutoff) * bsc);
                b = (b > 255) ? 255 : b;
                if (b == bstar) {
                    int p = atomicAdd(&s_cnt2, 1);
                    if (p < C2CAP) cand2[p] = make_float2(xi, s_ce[wseg + i]);
                }
            }
        }
        __syncthreads();                               // (5)
        const int C2 = s_cnt2;

        if (C2 <= C2CAP) {
            // ---------- E: exact all-pairs threshold within bin b* ----------
            float bx = 3.4e38f, bm = 0.f;
            for (int i = t; i < C2; i += TPB) {
                const float xi = cand2[i].x;
                float above = Ab, eq = 0.f;
                for (int j = 0; j < C2; j++) {
                    float2 cj = cand2[j];              // broadcast LDS.64
                    if (cj.x > xi) above += cj.y;
                    else if (cj.x == xi) eq += cj.y;
                }
                if (above <= target && xi < bx) { bx = xi; bm = above + eq; }
            }
            for (int o = 16; o; o >>= 1) {
                float ox = __shfl_xor_sync(0xffffffffu, bx, o);
                float om = __shfl_xor_sync(0xffffffffu, bm, o);
                if (ox < bx) { bx = ox; bm = om; }
            }
            if (lane == 0) { s_redS[warp] = bx; s_rm[warp] = bm; }
            __syncthreads();                           // (6) — also: all cand2 reads done
            float fx = s_redS[0], fm = s_rm[0];
            #pragma unroll
            for (int i = 1; i < NWP; i++)
                if (s_redS[i] < fx) { fx = s_redS[i]; fm = s_rm[i]; }
            xThr = fx; keptMass = fm;
        } else fb = true;
    }

    if (!fb) {
        const float rinv = 1.0f / fmaxf(keptMass, 1e-30f);

        // ---------- F: per-warp scatter kept probs + pack kept (x, idx) list ----------
        for (int base = 0; base < cnt; base += 32) {   // warp-uniform trip count
            int i = base + lane;
            float xi = (i < cnt) ? s_cx[wseg + i] : NEG_INF;
            bool kept = (i < cnt) && (xi >= xThr);
            int idx = 0;
            if (kept) {
                idx = s_cidx[wseg + i];
                prow[idx] = s_ce[wseg + i] * rinv;     // overwrite zero-fill
            }
            unsigned bal = __ballot_sync(0xffffffffu, kept);
            if (bal) {
                int ldr = __ffs(bal) - 1;
                int basep = 0;
                if (lane == ldr) basep = atomicAdd(&s_cnt3, __popc(bal));
                basep = __shfl_sync(0xffffffffu, basep, ldr);
                if (kept) {
                    int p = basep + __popc(bal & lmask);
                    if (p < KCAP) cand2[p] = make_float2(xi, __int_as_float(idx));
                }
            }
        }
        __syncthreads();                               // (7) kept list visible
        const int K = s_cnt3;

        if (K <= KCAP) {
            // ---------- G: warp 0 alone — Gumbel over packed kept list ----------
            if (warp == 0) {
                float best = NEG_INF;
                int   bidx = 0x7fffffff;
                for (int base = 0; base < K; base += 32) {
                    int i = base + lane;
                    if (i < K) {
                        float2 c = cand2[i];
                        int idx = __float_as_int(c.y);
                        float uu = __ldcs(&urow[idx]);
                        float g = -logf(-logf(uu));    // precise, kept-only
                        float val = c.x + g;
                        if (val > best || (val == best && idx < bidx)) { best = val; bidx = idx; }
                    }
                }
                for (int o = 16; o; o >>= 1) {
                    float v2 = __shfl_xor_sync(0xffffffffu, best, o);
                    int   i2 = __shfl_xor_sync(0xffffffffu, bidx, o);
                    if (v2 > best || (v2 == best && i2 < bidx)) { best = v2; bidx = i2; }
                }
                if (lane == 0) out_samp[row] = (float)bidx;
            }
        } else {
            // ---------- rare: many kept — per-warp Gumbel + block reduce (R13 path) ----------
            float best = NEG_INF;
            int   bidx = 0x7fffffff;
            for (int base = 0; base < cnt; base += 32) {
                int i = base + lane;
                if (i < cnt) {
                    float xi = s_cx[wseg + i];
                    if (xi >= xThr) {
                        int idx = s_cidx[wseg + i];
                        float uu = __ldcs(&urow[idx]);
                        float g = -logf(-logf(uu));
                        float val = xi + g;
                        if (val > best || (val == best && idx < bidx)) { best = val; bidx = idx; }
                    }
                }
            }
            for (int o = 16; o; o >>= 1) {
                float v2 = __shfl_xor_sync(0xffffffffu, best, o);
                int   i2 = __shfl_xor_sync(0xffffffffu, bidx, o);
                if (v2 > best || (v2 == best && i2 < bidx)) { best = v2; bidx = i2; }
            }
            if (lane == 0) { s_redM[warp] = best; s_wi[warp] = bidx; }
            __syncthreads();
            if (t == 0) {
                float bb = s_redM[0]; int bi = s_wi[0];
                #pragma unroll
                for (int i = 1; i < NWP; i++) {
                    float v2 = s_redM[i]; int i2 = s_wi[i];
                    if (v2 > bb || (v2 == bb && i2 < bi)) { bb = v2; bi = i2; }
                }
                out_samp[row] = (float)bi;
            }
        }
        return;
    }

    // ================= fallback: exact radix select (never hit; correct) =================
    {
        float zf = 0.f;
        #pragma unroll
        for (int j = 0; j < 4 * NITER; j++) zf += __expf(x[j] - m);
        for (int o = 16; o; o >>= 1) zf += __shfl_xor_sync(0xffffffffu, zf, o);
        __syncthreads();
        if (lane == 0) s_redZ[warp] = zf;
        __syncthreads();
        Z = s_redZ[0];
        #pragma unroll
        for (int i = 1; i < NWP; i++) Z += s_redZ[i];
        target = 0.95f * Z;

        unsigned hi = 0;
        float G = 0.f;
        float km = Z;
        #pragma unroll 1
        for (int pass = 3; pass >= 0; pass--) {
            __syncthreads();
            hist[t] = 0.f;
            if (t == 0) { s_flag = 0; s_fb = -1; s_digit = 0; s_G2 = 0.f; s_GB = 0.f; }
            __syncthreads();

            const int sh = pass * 8;
            #pragma unroll
            for (int j = 0; j < 4 * NITER; j++) {
                unsigned kk = fkey(x[j]);
                bool cnd = (pass == 3) ? true : ((kk >> (sh + 8)) == hi);
                if (cnd) atomicAdd(&hist[(kk >> sh) & 255u], __expf(x[j] - m));
            }
            __syncthreads();

            const int dgf = 255 - t;
            float vf = hist[dgf];
            float ivf = vf;
            #pragma unroll
            for (int o = 1; o < 32; o <<= 1) {
                float n = __shfl_up_sync(0xffffffffu, ivf, o);
                if (lane >= o) ivf += n;
            }
            if (lane == 31) s_redS[warp] = ivf;
            __syncthreads();
            float wof = 0.f;
            #pragma unroll
            for (int w = 0; w < NWP; w++) if (w < warp) wof += s_redS[w];
            const float inclf = wof + ivf;
            const float upf = __shfl_up_sync(0xffffffffu, inclf, 1);
            const float prevf = (lane == 0) ? wof : upf;

            const float tgt = target - G;
            if (inclf > tgt && prevf <= tgt) {
                s_digit = dgf; s_G2 = prevf; s_GB = prevf + vf; s_flag = 1;
            }
            __syncthreads();
            if (s_flag == 0 && vf > 0.f) atomicMax(&s_fb, t);
            __syncthreads();
            if (s_flag == 0 && t == s_fb) {
                s_digit = dgf; s_G2 = prevf; s_GB = prevf + vf;
            }
            __syncthreads();

            if (pass == 0) km = G + s_GB;
            G  = G + s_G2;
            hi = (hi << 8) | (unsigned)s_digit;
        }
        xThr = unkey(hi);
        keptMass = km;
    }

    {
        const float rinv = 1.0f / fmaxf(keptMass, 1e-30f);
        float best = NEG_INF;
        int   bidx = 0x7fffffff;
        #pragma unroll
        for (int k = 0; k < NITER; k++) {
            #pragma unroll
            for (int ci = 0; ci < 4; ci++) {
                int j = 4*k + ci;
                int idx = (k * TPB + t) * 4 + ci;
                if ((EXACT || idx < V) && x[j] >= xThr) {
                    prow[idx] = __expf(x[j] - m) * rinv;
                    float uu = __ldcs(&urow[idx]);
                    float g = -logf(-logf(uu));
                    float val = x[j] + g;
                    if (val > best || (val == best && idx < bidx)) { best = val; bidx = idx; }
                }
            }
        }
        for (int o = 16; o; o >>= 1) {
            float v2 = __shfl_xor_sync(0xffffffffu, best, o);
            int   i2 = __shfl_xor_sync(0xffffffffu, bidx, o);
            if (v2 > best || (v2 == best && i2 < bidx)) { best = v2; bidx = i2; }
        }
        if (lane == 0) { s_redM[warp] = best; s_wi[warp] = bidx; }
        __syncthreads();
        if (t == 0) {
            float bb = s_redM[0]; int bi = s_wi[0];
            #pragma unroll
            for (int i = 1; i < NWP; i++) {
                float v2 = s_redM[i]; int i2 = s_wi[i];
                if (v2 > bb || (v2 == bb && i2 < bi)) { bb = v2; bi = i2; }
            }
            out_samp[row] = (float)bi;
        }
    }
}

extern "C" void kernel_launch(void* const* d_in, const int* in_sizes, int n_in,
                              void* d_out, int out_size) {
    const float* logits = (const float*)d_in[0];
    const float* u      = (const float*)d_in[1];
    float* out = (float*)d_out;

    int total = in_sizes[0];
    int B = out_size - total;
    int V;
    if (B > 0 && total % B == 0) {
        V = total / B;
    } else {
        V = 2048;
        B = total / V;
    }
    int NV4 = V / 4;
    int nIter = (NV4 + TPB - 1) / TPB;

    if (nIter <= 1) {
        if (NV4 == 1 * TPB) sampler_kernel<1, true><<<B, TPB>>>(logits, u, out, out + B, NV4);
        else                sampler_kernel<1, false><<<B, TPB>>>(logits, u, out, out + B, NV4);
    } else if (nIter <= 2) {
        if (NV4 == 2 * TPB) sampler_kernel<2, true><<<B, TPB>>>(logits, u, out, out + B, NV4);
        else                sampler_kernel<2, false><<<B, TPB>>>(logits, u, out, out + B, NV4);
    } else if (nIter <= 4) {
        if (NV4 == 4 * TPB) sampler_kernel<4, true><<<B, TPB>>>(logits, u, out, out + B, NV4);
        else                sampler_kernel<4, false><<<B, TPB>>>(logits, u, out, out + B, NV4);
    } else {
        if (NV4 == 8 * TPB) sampler_kernel<8, true><<<B, TPB>>>(logits, u, out, out + B, NV4);
        else                sampler_kernel<8, false><<<B, TPB>>>(logits, u, out, out + B, NV4);
    }
}